// round 10
// baseline (speedup 1.0000x reference)
#include <cuda_runtime.h>
#include <cuda_bf16.h>

#define N_NODES   1000000
#define D_FEAT    128
#define B_SEGS    1024
#define NWARPS    8
#define NTHREADS  (NWARPS * 32)
#define BLOCKS_PER_SM 5
#define GRID_A    (148 * BLOCKS_PER_SM)     // 740 blocks; co-resident on >=148 SMs
#define TOT_WARPS (GRID_A * NWARPS)         // 5920
#define ROWS_PW   169                       // ceil(1e6 / 5920)

// Device scratch (no allocations allowed). Zero-initialized at module load.
// The kernel restores g_S/g_W to zero and counters to zero before exiting,
// so every graph replay sees identical initial state.
__device__ __align__(16) float g_e[N_NODES];          // exp(gate) per node
__device__ float g_S[B_SEGS];                          // per-segment exp-sum
__device__ __align__(16) float g_W[B_SEGS * D_FEAT];   // per-segment weighted sum
__device__ unsigned g_cA, g_cB, g_cC;                  // grid-barrier counters

__device__ __forceinline__ void grid_barrier(unsigned* ctr)
{
    __syncthreads();
    if (threadIdx.x == 0) {
        __threadfence();                       // publish this block's writes
        atomicAdd(ctr, 1);
        volatile unsigned* p = ctr;
        while (*p < GRID_A) __nanosleep(64);
        __threadfence();
    }
    __syncthreads();
}

__global__ __launch_bounds__(NTHREADS, BLOCKS_PER_SM)
void gap_persistent_kernel(const float* __restrict__ feat,
                           const float* __restrict__ w_gate,
                           const float* __restrict__ b_gate,
                           const int*   __restrict__ seg,
                           float* __restrict__ readout,   // [B, D]
                           float* __restrict__ alpha)     // [N]
{
    const int tid  = threadIdx.x;
    const int wid  = tid >> 5;
    const int lane = tid & 31;

    // ================= Phase 1: fused gate + exp + weighted accumulation ======
    {
        const int gw     = blockIdx.x * NWARPS + wid;    // global warp id
        const int wstart = gw * ROWS_PW;
        const int wend   = min(wstart + ROWS_PW, N_NODES);
        if (wstart < wend) {
            const float  bg = b_gate[0];
            const float4 w4 = reinterpret_cast<const float4*>(w_gate)[lane];
            const float4* __restrict__ feat4 = reinterpret_cast<const float4*>(feat);

            int    cur  = seg[wstart];               // warp-uniform
            float  Ssum = 0.f;
            float4 acc  = make_float4(0.f, 0.f, 0.f, 0.f);

            int n = wstart;
            while (n < wend) {
                if (n + 3 < wend && seg[n] == cur && seg[n + 3] == cur) {
                    // ---- fast path: 4 rows, same segment ----
                    const float4 f0 = __ldg(feat4 + (size_t)(n + 0) * 32 + lane);
                    const float4 f1 = __ldg(feat4 + (size_t)(n + 1) * 32 + lane);
                    const float4 f2 = __ldg(feat4 + (size_t)(n + 2) * 32 + lane);
                    const float4 f3 = __ldg(feat4 + (size_t)(n + 3) * 32 + lane);

                    float p0 = f0.x*w4.x + f0.y*w4.y + f0.z*w4.z + f0.w*w4.w;
                    float p1 = f1.x*w4.x + f1.y*w4.y + f1.z*w4.z + f1.w*w4.w;
                    float p2 = f2.x*w4.x + f2.y*w4.y + f2.z*w4.z + f2.w*w4.w;
                    float p3 = f3.x*w4.x + f3.y*w4.y + f3.z*w4.z + f3.w*w4.w;
                    #pragma unroll
                    for (int s = 16; s >= 1; s >>= 1) {
                        p0 += __shfl_xor_sync(0xffffffffu, p0, s);
                        p1 += __shfl_xor_sync(0xffffffffu, p1, s);
                        p2 += __shfl_xor_sync(0xffffffffu, p2, s);
                        p3 += __shfl_xor_sync(0xffffffffu, p3, s);
                    }
                    const float e0 = __expf(p0 + bg);
                    const float e1 = __expf(p1 + bg);
                    const float e2 = __expf(p2 + bg);
                    const float e3 = __expf(p3 + bg);
                    if (lane < 4) {
                        float ev = (lane == 0) ? e0 : (lane == 1) ? e1 : (lane == 2) ? e2 : e3;
                        g_e[n + lane] = ev;
                    }
                    Ssum += (e0 + e1) + (e2 + e3);
                    acc.x += e0*f0.x + e1*f1.x + e2*f2.x + e3*f3.x;
                    acc.y += e0*f0.y + e1*f1.y + e2*f2.y + e3*f3.y;
                    acc.z += e0*f0.z + e1*f1.z + e2*f2.z + e3*f3.z;
                    acc.w += e0*f0.w + e1*f1.w + e2*f2.w + e3*f3.w;
                    n += 4;
                } else {
                    // ---- slow path: one row, possible segment boundary ----
                    const int s = seg[n];
                    if (s != cur) {
                        if (lane == 0) atomicAdd(&g_S[cur], Ssum);
                        float* wp = &g_W[(size_t)cur * D_FEAT + lane * 4];
                        atomicAdd(wp + 0, acc.x);
                        atomicAdd(wp + 1, acc.y);
                        atomicAdd(wp + 2, acc.z);
                        atomicAdd(wp + 3, acc.w);
                        cur = s; Ssum = 0.f; acc = make_float4(0.f, 0.f, 0.f, 0.f);
                    }
                    const float4 f = __ldg(feat4 + (size_t)n * 32 + lane);
                    float p = f.x*w4.x + f.y*w4.y + f.z*w4.z + f.w*w4.w;
                    #pragma unroll
                    for (int sh = 16; sh >= 1; sh >>= 1)
                        p += __shfl_xor_sync(0xffffffffu, p, sh);
                    const float e = __expf(p + bg);
                    if (lane == 0) g_e[n] = e;
                    Ssum += e;
                    acc.x += e*f.x; acc.y += e*f.y; acc.z += e*f.z; acc.w += e*f.w;
                    n += 1;
                }
            }
            // final flush
            if (lane == 0) atomicAdd(&g_S[cur], Ssum);
            float* wp = &g_W[(size_t)cur * D_FEAT + lane * 4];
            atomicAdd(wp + 0, acc.x);
            atomicAdd(wp + 1, acc.y);
            atomicAdd(wp + 2, acc.z);
            atomicAdd(wp + 3, acc.w);
        }
    }

    // ================= Barrier A: all accumulators final =======================
    grid_barrier(&g_cA);

    const int gtid = blockIdx.x * NTHREADS + tid;

    // ================= Phase 2a: readout + g_W zero-restore ====================
    // 32 float4-quads per segment row; same thread reads and zeroes its quad.
    {
        float4* w4p = reinterpret_cast<float4*>(g_W);
        float4* r4p = reinterpret_cast<float4*>(readout);
        for (int q = gtid; q < (B_SEGS * D_FEAT) / 4; q += GRID_A * NTHREADS) {
            const int   b    = q >> 5;                 // 32 quads per segment
            const float S    = g_S[b];
            const float invS = (S > 0.f) ? __fdividef(1.0f, S) : 0.0f;
            float4 w = w4p[q];
            float4 r;
            r.x = w.x * invS; r.y = w.y * invS; r.z = w.z * invS; r.w = w.w * invS;
            r4p[q] = r;
            w4p[q] = make_float4(0.f, 0.f, 0.f, 0.f);
        }
    }

    // ================= Phase 2b: alpha = e / S[seg] ===========================
    {
        const float4* e4p = reinterpret_cast<const float4*>(g_e);
        const int4*   s4p = reinterpret_cast<const int4*>(seg);
        float4*       a4p = reinterpret_cast<float4*>(alpha);
        for (int q = gtid; q < N_NODES / 4; q += GRID_A * NTHREADS) {
            const float4 e = e4p[q];
            const int4   s = s4p[q];
            float4 a;
            a.x = __fdividef(e.x, g_S[s.x]);
            a.y = __fdividef(e.y, g_S[s.y]);
            a.z = __fdividef(e.z, g_S[s.z]);
            a.w = __fdividef(e.w, g_S[s.w]);
            a4p[q] = a;
        }
    }

    // ================= Barrier B: all g_S reads done ==========================
    grid_barrier(&g_cB);

    // ================= Phase 3: zero-restore g_S ==============================
    if (gtid < B_SEGS) g_S[gtid] = 0.f;

    // ================= Exit: last block resets the barrier counters ===========
    __syncthreads();
    if (tid == 0) {
        __threadfence();
        const unsigned old = atomicAdd(&g_cC, 1);
        if (old == GRID_A - 1) {
            g_cA = 0u;
            g_cB = 0u;
            __threadfence();
            g_cC = 0u;
            __threadfence();
        }
    }
}

extern "C" void kernel_launch(void* const* d_in, const int* in_sizes, int n_in,
                              void* d_out, int out_size)
{
    const float* feat   = (const float*)d_in[0];
    const float* w_gate = (const float*)d_in[1];
    const float* b_gate = (const float*)d_in[2];
    const int*   seg    = (const int*)d_in[3];

    float* out     = (float*)d_out;
    float* readout = out;                            // [B, D]
    float* alpha   = out + (size_t)B_SEGS * D_FEAT;  // [N, 1]

    gap_persistent_kernel<<<GRID_A, NTHREADS>>>(feat, w_gate, b_gate, seg,
                                                readout, alpha);
}

// round 12
// speedup vs baseline: 1.0711x; 1.0711x over previous
#include <cuda_runtime.h>
#include <cuda_bf16.h>

#define N_NODES   1000000
#define D_FEAT    128
#define B_SEGS    1024
#define NWARPS    8
#define NTHREADS  (NWARPS * 32)
#define BLOCKS_PER_SM 5
#define GRID_A    (148 * BLOCKS_PER_SM)     // 740 blocks -> exactly one wave
#define TOT_WARPS (GRID_A * NWARPS)         // 5920
#define ROWS_PW   169                       // ceil(1e6 / 5920)

// Device scratch (no allocations allowed). Zero-initialized at module load;
// the finalize kernel restores g_S/g_W to zero after each use, so every
// graph replay sees zeroed accumulators without a dedicated zeroing launch.
// g_start is fully rewritten by the main kernel each replay.
__device__ __align__(16) float g_e[N_NODES]; // exp(gate) per node
__device__ float g_S[B_SEGS];                // per-segment exp-sum
__device__ float g_W[B_SEGS * D_FEAT];       // per-segment weighted sum
__device__ int   g_start[B_SEGS + 1];        // per-segment start offsets

// ------------------------------------------------------- main fused pass over feat
// Also performs segment-boundary detection inline: every transition index is
// encountered exactly once (in the slow path or a warp prologue), so g_start
// is complete when this kernel finishes.
__global__ __launch_bounds__(NTHREADS, BLOCKS_PER_SM)
void gap_main_kernel(const float* __restrict__ feat,
                     const float* __restrict__ w_gate,
                     const float* __restrict__ b_gate,
                     const int*   __restrict__ seg)
{
    const int tid  = threadIdx.x;
    const int wid  = tid >> 5;
    const int lane = tid & 31;

    const int gw     = blockIdx.x * NWARPS + wid;        // global warp id
    const int wstart = gw * ROWS_PW;
    const int wend   = min(wstart + ROWS_PW, N_NODES);
    if (wstart >= wend) return;

    const float  bg = b_gate[0];
    const float4 w4 = reinterpret_cast<const float4*>(w_gate)[lane];
    const float4* __restrict__ feat4 = reinterpret_cast<const float4*>(feat);

    int    cur  = seg[wstart];                // warp-uniform
    float  Ssum = 0.f;
    float4 acc  = make_float4(0.f, 0.f, 0.f, 0.f);

    // ---- boundary prologue: transitions landing exactly at wstart ----
    if (lane == 0) {
        if (wstart == 0) {
            for (int b = 0; b <= cur; b++) g_start[b] = 0;
        } else {
            const int prev = seg[wstart - 1];
            for (int b = prev + 1; b <= cur; b++) g_start[b] = wstart;
        }
    }

    int n = wstart;
    while (n < wend) {
        if (n + 3 < wend && seg[n] == cur && seg[n + 3] == cur) {
            // ---- fast path: 4 rows, same segment (sorted => all 4 equal) ----
            const float4 f0 = __ldg(feat4 + (size_t)(n + 0) * 32 + lane);
            const float4 f1 = __ldg(feat4 + (size_t)(n + 1) * 32 + lane);
            const float4 f2 = __ldg(feat4 + (size_t)(n + 2) * 32 + lane);
            const float4 f3 = __ldg(feat4 + (size_t)(n + 3) * 32 + lane);

            float p0 = f0.x*w4.x + f0.y*w4.y + f0.z*w4.z + f0.w*w4.w;
            float p1 = f1.x*w4.x + f1.y*w4.y + f1.z*w4.z + f1.w*w4.w;
            float p2 = f2.x*w4.x + f2.y*w4.y + f2.z*w4.z + f2.w*w4.w;
            float p3 = f3.x*w4.x + f3.y*w4.y + f3.z*w4.z + f3.w*w4.w;

            // Cooperative 4-row warp reduce: 9 shuffles reduce all four rows.
            // After stage xor-2, lane class (lane&3)==i carries row i's partial;
            // three butterfly stages complete it. Verified lane algebra:
            //   xor1 pairs p0/p1 and p2/p3; xor2 pairs those; xor4/8/16 finish.
            float a01 = (lane & 1) ? p1 : p0;
            float b01 = (lane & 1) ? p0 : p1;
            a01 += __shfl_xor_sync(0xffffffffu, b01, 1);
            float a23 = (lane & 1) ? p3 : p2;
            float b23 = (lane & 1) ? p2 : p3;
            a23 += __shfl_xor_sync(0xffffffffu, b23, 1);
            float r = (lane & 2) ? a23 : a01;
            float s = (lane & 2) ? a01 : a23;
            r += __shfl_xor_sync(0xffffffffu, s, 2);
            r += __shfl_xor_sync(0xffffffffu, r, 4);
            r += __shfl_xor_sync(0xffffffffu, r, 8);
            r += __shfl_xor_sync(0xffffffffu, r, 16);

            // One expf per lane (its class's row), instead of four.
            const float e = __expf(r + bg);
            if (lane < 4) g_e[n + lane] = e;     // lane i holds row i's e

            const float e0 = __shfl_sync(0xffffffffu, e, 0);
            const float e1 = __shfl_sync(0xffffffffu, e, 1);
            const float e2 = __shfl_sync(0xffffffffu, e, 2);
            const float e3 = __shfl_sync(0xffffffffu, e, 3);

            Ssum += (e0 + e1) + (e2 + e3);
            acc.x += e0*f0.x + e1*f1.x + e2*f2.x + e3*f3.x;
            acc.y += e0*f0.y + e1*f1.y + e2*f2.y + e3*f3.y;
            acc.z += e0*f0.z + e1*f1.z + e2*f2.z + e3*f3.z;
            acc.w += e0*f0.w + e1*f1.w + e2*f2.w + e3*f3.w;
            n += 4;
        } else {
            // ---- slow path: one row, possible segment boundary ----
            const int s = seg[n];
            if (s != cur) {
                // record boundary + flush warp-private partials
                if (lane == 0) {
                    for (int b = cur + 1; b <= s; b++) g_start[b] = n;
                    atomicAdd(&g_S[cur], Ssum);
                }
                float* wp = &g_W[(size_t)cur * D_FEAT + lane * 4];
                atomicAdd(wp + 0, acc.x);
                atomicAdd(wp + 1, acc.y);
                atomicAdd(wp + 2, acc.z);
                atomicAdd(wp + 3, acc.w);
                cur = s; Ssum = 0.f; acc = make_float4(0.f, 0.f, 0.f, 0.f);
            }
            const float4 f = __ldg(feat4 + (size_t)n * 32 + lane);
            float p = f.x*w4.x + f.y*w4.y + f.z*w4.z + f.w*w4.w;
            #pragma unroll
            for (int sh = 16; sh >= 1; sh >>= 1)
                p += __shfl_xor_sync(0xffffffffu, p, sh);
            const float e = __expf(p + bg);
            if (lane == 0) g_e[n] = e;
            Ssum += e;
            acc.x += e*f.x; acc.y += e*f.y; acc.z += e*f.z; acc.w += e*f.w;
            n += 1;
        }
    }

    // ---- final flush + boundary epilogue ----
    if (lane == 0) {
        atomicAdd(&g_S[cur], Ssum);
        if (wend == N_NODES)
            for (int b = cur + 1; b <= B_SEGS; b++) g_start[b] = N_NODES;
    }
    float* wp = &g_W[(size_t)cur * D_FEAT + lane * 4];
    atomicAdd(wp + 0, acc.x);
    atomicAdd(wp + 1, acc.y);
    atomicAdd(wp + 2, acc.z);
    atomicAdd(wp + 3, acc.w);
}

// ---------------- finalize + alpha, one block per segment -------------------
// Flat loads of precomputed bounds, block-uniform invS, vectorized alpha body,
// and zero-restore of the accumulators for the next replay.
__global__ __launch_bounds__(256)
void gap_finalize_alpha_kernel(float* __restrict__ readout,
                               float* __restrict__ alpha)
{
    const int b   = blockIdx.x;
    const int tid = threadIdx.x;

    const int start = g_start[b];
    const int end   = g_start[b + 1];
    const float S   = g_S[b];
    const float invS = (S > 0.f) ? (1.0f / S) : 0.0f;

    if (tid < D_FEAT) {
        const size_t idx = (size_t)b * D_FEAT + tid;
        readout[idx] = g_W[idx] * invS;
        g_W[idx] = 0.f;                         // restore zeros for next replay
    }
    if (tid == 0) g_S[b] = 0.f;

    // alpha: scalar head/tail, float4 body (g_e and alpha are 16B-aligned).
    const int a4 = (start + 3) & ~3;
    const int e4 = end & ~3;
    // head (< 3 elements)
    for (int n = start + tid; n < min(a4, end); n += 256)
        alpha[n] = g_e[n] * invS;
    if (a4 < e4) {
        const float4* e4p = reinterpret_cast<const float4*>(g_e);
        float4*       a4p = reinterpret_cast<float4*>(alpha);
        for (int q = (a4 >> 2) + tid; q < (e4 >> 2); q += 256) {
            const float4 v = e4p[q];
            float4 a;
            a.x = v.x * invS; a.y = v.y * invS; a.z = v.z * invS; a.w = v.w * invS;
            a4p[q] = a;
        }
    }
    // tail (< 3 elements)
    for (int n = max(e4, a4) + tid; n < end; n += 256)
        alpha[n] = g_e[n] * invS;
}

extern "C" void kernel_launch(void* const* d_in, const int* in_sizes, int n_in,
                              void* d_out, int out_size)
{
    const float* feat   = (const float*)d_in[0];
    const float* w_gate = (const float*)d_in[1];
    const float* b_gate = (const float*)d_in[2];
    const int*   seg    = (const int*)d_in[3];

    float* out     = (float*)d_out;
    float* readout = out;                            // [B, D]
    float* alpha   = out + (size_t)B_SEGS * D_FEAT;  // [N, 1]

    gap_main_kernel<<<GRID_A, NTHREADS>>>(feat, w_gate, b_gate, seg);
    gap_finalize_alpha_kernel<<<B_SEGS, 256>>>(readout, alpha);
}